// round 12
// baseline (speedup 1.0000x reference)
#include <cuda_runtime.h>
#include <math.h>
#include <stdint.h>

#define NMAX 100000
#define EMAX 2000000
#define EPSBN 1e-5f

// ---------------- scratch (device globals: no allocations allowed) ----------
__device__ float g_agg[(size_t)NMAX * 256];   // aggregation buffer (tf32-rounded)
__device__ float g_h1[(size_t)NMAX * 128];    // layer-1 output (tf32-rounded)
__device__ float g_h2[(size_t)NMAX * 256];    // layer-2 output (tf32-rounded)
__device__ float g_wr[229376];                // tf32-rounded weights ([K][N] layout)
__device__ int   g_cnt[NMAX];
__device__ int   g_off[NMAX + 1];
__device__ int   g_cur[NMAX];
__device__ int   g_csr[EMAX];
__device__ float g_invdeg[NMAX];

// ---------------- helpers -----------------------------------------------------
__device__ __forceinline__ unsigned f2tf(float f) {
    unsigned u;
    asm("cvt.rna.tf32.f32 %0, %1;" : "=r"(u) : "f"(f));
    return u;
}
__device__ __forceinline__ float tf32r(float f) { return __uint_as_float(f2tf(f)); }

__device__ __forceinline__ void mma_tf32(float* c, const unsigned* a, const unsigned* b) {
    asm volatile(
        "mma.sync.aligned.m16n8k8.row.col.f32.tf32.tf32.f32 "
        "{%0,%1,%2,%3}, {%4,%5,%6,%7}, {%8,%9}, {%0,%1,%2,%3};"
        : "+f"(c[0]), "+f"(c[1]), "+f"(c[2]), "+f"(c[3])
        : "r"(a[0]), "r"(a[1]), "r"(a[2]), "r"(a[3]), "r"(b[0]), "r"(b[1]));
}

__device__ __forceinline__ void cp16(void* dst, const void* src) {
    unsigned d = (unsigned)__cvta_generic_to_shared(dst);
    asm volatile("cp.async.cg.shared.global [%0], [%1], 16;" :: "r"(d), "l"(src));
}
__device__ __forceinline__ void cp_commit() { asm volatile("cp.async.commit_group;"); }
template<int N>
__device__ __forceinline__ void cp_wait() { asm volatile("cp.async.wait_group %0;" :: "n"(N)); }

// ---------------- CSR build --------------------------------------------------
__global__ void hist_kernel(const int* __restrict__ dst, int E) {
    int i = blockIdx.x * blockDim.x + threadIdx.x;
    if (i < E) atomicAdd(&g_cnt[dst[i]], 1);
}

__global__ void scan_kernel(int M) {
    __shared__ int part[1024];
    const int t = threadIdx.x;
    const int chunk = (M + 1023) >> 10;
    const int beg = t * chunk;
    const int end = min(beg + chunk, M);
    int s = 0;
    for (int i = beg; i < end; i++) s += g_cnt[i];
    part[t] = s;
    __syncthreads();
    for (int ofs = 1; ofs < 1024; ofs <<= 1) {
        int v = (t >= ofs) ? part[t - ofs] : 0;
        __syncthreads();
        part[t] += v;
        __syncthreads();
    }
    int run = (t > 0) ? part[t - 1] : 0;
    for (int i = beg; i < end; i++) {
        g_off[i] = run;
        g_cur[i] = run;
        g_invdeg[i] = 1.0f / fmaxf((float)g_cnt[i], 1.0f);
        run += g_cnt[i];
    }
    if (end == M) g_off[M] = run;
}

__global__ void fill_kernel(const int* __restrict__ src,
                            const int* __restrict__ dst, int E) {
    int i = blockIdx.x * blockDim.x + threadIdx.x;
    if (i < E) {
        int d = dst[i];
        int pos = atomicAdd(&g_cur[d], 1);
        g_csr[pos] = src[i];
    }
}

// ---------------- setup: tf32-rounded weights --------------------------------
__global__ void prep_weights(const float* __restrict__ w1l, const float* __restrict__ w1r,
                             const float* __restrict__ w2l, const float* __restrict__ w2r,
                             const float* __restrict__ w3l, const float* __restrict__ w3r) {
    const int seg = blockIdx.y;
    const float* src;
    float* dst;
    int n;
    switch (seg) {
        case 0:  src = w1l; dst = g_wr + 0;      n = 16384; break;
        case 1:  src = w1r; dst = g_wr + 16384;  n = 16384; break;
        case 2:  src = w2l; dst = g_wr + 32768;  n = 32768; break;
        case 3:  src = w2r; dst = g_wr + 65536;  n = 32768; break;
        case 4:  src = w3l; dst = g_wr + 98304;  n = 65536; break;
        default: src = w3r; dst = g_wr + 163840; n = 65536; break;
    }
    int i = blockIdx.x * blockDim.x + threadIdx.x;
    if (i < n) dst[i] = tf32r(src[i]);   // same [K][NOUT] layout, rounded
}

// ---------------- CSR gather: agg[n,:] = round_tf32(mean h[src,:]) -----------
// One warp per node; neighbor loop unrolled x2 for MLP.
template<int D>
__global__ void gather_kernel(const float* __restrict__ h,
                              float* __restrict__ agg, int M) {
    const int warp = (blockIdx.x * blockDim.x + threadIdx.x) >> 5;
    const int lane = threadIdx.x & 31;
    if (warp >= M) return;
    const int beg = g_off[warp];
    const int end = g_off[warp + 1];

    float4 a0 = make_float4(0.f, 0.f, 0.f, 0.f);
    float4 a1 = make_float4(0.f, 0.f, 0.f, 0.f);

    for (int j0 = beg; j0 < end; j0 += 32) {
        const int myi = (j0 + lane < end) ? g_csr[j0 + lane] : 0;
        const int cnt = min(32, end - j0);
        int t = 0;
        for (; t + 1 < cnt; t += 2) {
            const int s0 = __shfl_sync(0xffffffffu, myi, t);
            const int s1 = __shfl_sync(0xffffffffu, myi, t + 1);
            const float4* r0 = (const float4*)(h + (size_t)s0 * D);
            const float4* r1 = (const float4*)(h + (size_t)s1 * D);
            const float4 v0 = r0[lane];
            const float4 v1 = r1[lane];
            a0.x += v0.x; a0.y += v0.y; a0.z += v0.z; a0.w += v0.w;
            a0.x += v1.x; a0.y += v1.y; a0.z += v1.z; a0.w += v1.w;
            if (D == 256) {
                const float4 w0 = r0[lane + 32];
                const float4 w1 = r1[lane + 32];
                a1.x += w0.x; a1.y += w0.y; a1.z += w0.z; a1.w += w0.w;
                a1.x += w1.x; a1.y += w1.y; a1.z += w1.z; a1.w += w1.w;
            }
        }
        if (t < cnt) {
            const int s0 = __shfl_sync(0xffffffffu, myi, t);
            const float4* r0 = (const float4*)(h + (size_t)s0 * D);
            const float4 v0 = r0[lane];
            a0.x += v0.x; a0.y += v0.y; a0.z += v0.z; a0.w += v0.w;
            if (D == 256) {
                const float4 w0 = r0[lane + 32];
                a1.x += w0.x; a1.y += w0.y; a1.z += w0.z; a1.w += w0.w;
            }
        }
    }
    const float s = g_invdeg[warp];
    float4* outr = (float4*)(agg + (size_t)warp * D);
    outr[lane] = make_float4(tf32r(a0.x * s), tf32r(a0.y * s),
                             tf32r(a0.z * s), tf32r(a0.w * s));
    if (D == 256) {
        outr[lane + 32] = make_float4(tf32r(a1.x * s), tf32r(a1.y * s),
                                      tf32r(a1.z * s), tf32r(a1.w * s));
    }
}

// ---------------- fused dual GEMM (mma.sync, pre-rounded) + bias/ReLU/BN -----
// C = BN(ReLU( Aagg @ Wl + Aself @ Wr + bias ))
// Aagg/Wl/Wr pre-rounded to tf32; Aself rounded in-loop iff cvt_self (layer 1).
// Block 128x128, 256 threads (8 warps 2x4), warp tile 64x32, BK=16, 4 stages.
#define STAGES 4
#define A_PITCH 20
#define B_PITCH 136
#define A_STRIDE (128 * A_PITCH)
#define B_STRIDE (16 * B_PITCH)
#define GEMM_SMEM ((STAGES * (A_STRIDE + B_STRIDE)) * 4)

template<int K, int NOUT>
__global__ void __launch_bounds__(256, 2)
gemm_tc(const float* __restrict__ Aagg,
        const float* __restrict__ Aself,
        const float* __restrict__ Wl,
        const float* __restrict__ Wr,
        const float* __restrict__ bias,
        const float* __restrict__ gam,
        const float* __restrict__ bet,
        const float* __restrict__ mu,
        const float* __restrict__ var,
        float* __restrict__ C, int M, int round_out, int cvt_self) {
    extern __shared__ float sm[];
    float* As = sm;                          // [STAGES][128][A_PITCH]
    float* Bs = sm + STAGES * A_STRIDE;      // [STAGES][16][B_PITCH]

    const int tid  = threadIdx.x;
    const int lane = tid & 31;
    const int wid  = tid >> 5;
    const int wm   = wid & 1;          // warp row (0..1) -> 64 rows
    const int wn   = wid >> 1;         // warp col (0..3) -> 32 cols
    const int row0 = blockIdx.x * 128;
    const int col0 = blockIdx.y * 128;

    // cp.async mappings: A 128x16 (2 x 16B/thread), B 16x128 (2 x 16B/thread)
    const int ar = tid >> 2;           // 0..63 (rows ar, ar+64)
    const int ac = (tid & 3) << 2;     // 0,4,8,12
    const int br = tid >> 5;           // 0..7  (rows br, br+8)
    const int bc = lane << 2;          // 0..124

    const int gr0 = min(row0 + ar, M - 1);
    const int gr1 = min(row0 + ar + 64, M - 1);

    float acc[4][4][4];
    #pragma unroll
    for (int i = 0; i < 4; i++)
        #pragma unroll
        for (int j = 0; j < 4; j++)
            #pragma unroll
            for (int q = 0; q < 4; q++) acc[i][j][q] = 0.0f;

    const int PH  = K / 16;
    const int NIT = 2 * PH;

    auto ISSUE = [&](int it, int st) {
        const int ph = (it >= PH) ? 1 : 0;
        const int kb = (ph ? it - PH : it) * 16;
        const float* A = ph ? Aself : Aagg;
        const float* W = ph ? Wr : Wl;
        float* as = As + st * A_STRIDE;
        float* bs = Bs + st * B_STRIDE;
        cp16(as + ar * A_PITCH + ac,        A + (size_t)gr0 * K + kb + ac);
        cp16(as + (ar + 64) * A_PITCH + ac, A + (size_t)gr1 * K + kb + ac);
        cp16(bs + br * B_PITCH + bc,        W + (size_t)(kb + br)     * NOUT + col0 + bc);
        cp16(bs + (br + 8) * B_PITCH + bc,  W + (size_t)(kb + br + 8) * NOUT + col0 + bc);
    };

    const int fr = lane >> 2;          // fragment row / B col
    const int fc = lane & 3;           // fragment k col

    auto COMPUTE = [&](int st, bool cv) {
        const float* as = As + st * A_STRIDE;
        const float* bs = Bs + st * B_STRIDE;
        #pragma unroll
        for (int ks = 0; ks < 2; ++ks) {
            const int kk = ks * 8;
            unsigned af[4][4], bf[4][2];
            #pragma unroll
            for (int mi = 0; mi < 4; mi++) {
                const int rb = wm * 64 + mi * 16;
                float f0 = as[(rb + fr)     * A_PITCH + kk + fc];
                float f1 = as[(rb + fr + 8) * A_PITCH + kk + fc];
                float f2 = as[(rb + fr)     * A_PITCH + kk + fc + 4];
                float f3 = as[(rb + fr + 8) * A_PITCH + kk + fc + 4];
                if (cv) {
                    af[mi][0] = f2tf(f0); af[mi][1] = f2tf(f1);
                    af[mi][2] = f2tf(f2); af[mi][3] = f2tf(f3);
                } else {
                    af[mi][0] = __float_as_uint(f0); af[mi][1] = __float_as_uint(f1);
                    af[mi][2] = __float_as_uint(f2); af[mi][3] = __float_as_uint(f3);
                }
            }
            #pragma unroll
            for (int ni = 0; ni < 4; ni++) {
                const int cb = wn * 32 + ni * 8 + fr;
                bf[ni][0] = __float_as_uint(bs[(kk + fc)     * B_PITCH + cb]);
                bf[ni][1] = __float_as_uint(bs[(kk + fc + 4) * B_PITCH + cb]);
            }
            #pragma unroll
            for (int mi = 0; mi < 4; mi++)
                #pragma unroll
                for (int ni = 0; ni < 4; ni++)
                    mma_tf32(acc[mi][ni], af[mi], bf[ni]);
        }
    };

    #pragma unroll
    for (int s = 0; s < STAGES - 1; ++s) {
        ISSUE(s, s);
        cp_commit();
    }

    for (int it = 0; it < NIT; ++it) {
        cp_wait<STAGES - 2>();
        __syncthreads();
        const int nx = it + STAGES - 1;
        if (nx < NIT) ISSUE(nx, nx % STAGES);
        cp_commit();
        COMPUTE(it % STAGES, cvt_self && (it >= PH));
    }

    // epilogue: bias -> ReLU -> BatchNorm(eval), optional tf32 rounding
    float sc[4][2], sh[4][2], bb[4][2];
    int   cbs[4];
    #pragma unroll
    for (int ni = 0; ni < 4; ni++) {
        const int cb = col0 + wn * 32 + ni * 8 + ((lane & 3) << 1);
        cbs[ni] = cb;
        #pragma unroll
        for (int j = 0; j < 2; j++) {
            const int c = cb + j;
            const float rs = rsqrtf(var[c] + EPSBN);
            sc[ni][j] = gam[c] * rs;
            sh[ni][j] = bet[c] - mu[c] * sc[ni][j];
            bb[ni][j] = bias[c];
        }
    }
    #pragma unroll
    for (int mi = 0; mi < 4; mi++) {
        const int rbase = row0 + wm * 64 + mi * 16 + (lane >> 2);
        #pragma unroll
        for (int h = 0; h < 2; h++) {
            const int r = rbase + h * 8;
            if (r < M) {
                #pragma unroll
                for (int ni = 0; ni < 4; ni++) {
                    float z0 = acc[mi][ni][h * 2 + 0] + bb[ni][0];
                    float z1 = acc[mi][ni][h * 2 + 1] + bb[ni][1];
                    z0 = fmaxf(z0, 0.0f) * sc[ni][0] + sh[ni][0];
                    z1 = fmaxf(z1, 0.0f) * sc[ni][1] + sh[ni][1];
                    float2 o;
                    o.x = round_out ? tf32r(z0) : z0;
                    o.y = round_out ? tf32r(z1) : z1;
                    *(float2*)(C + (size_t)r * NOUT + cbs[ni]) = o;
                }
            }
        }
    }
}

// ---------------- launcher ---------------------------------------------------
extern "C" void kernel_launch(void* const* d_in, const int* in_sizes, int n_in,
                              void* d_out, int out_size) {
    const float* x   = (const float*)d_in[0];
    const int*   ei  = (const int*)d_in[1];
    const int    E   = in_sizes[1] / 2;
    const int    M   = in_sizes[0] / 128;
    const int*   src = ei;
    const int*   dst = ei + E;

    const float* w1l = (const float*)d_in[2];
    const float* w1r = (const float*)d_in[3];
    const float* b1  = (const float*)d_in[4];
    const float* ga1 = (const float*)d_in[5];
    const float* be1 = (const float*)d_in[6];
    const float* m1  = (const float*)d_in[7];
    const float* v1  = (const float*)d_in[8];
    const float* w2l = (const float*)d_in[9];
    const float* w2r = (const float*)d_in[10];
    const float* b2  = (const float*)d_in[11];
    const float* ga2 = (const float*)d_in[12];
    const float* be2 = (const float*)d_in[13];
    const float* m2  = (const float*)d_in[14];
    const float* v2  = (const float*)d_in[15];
    const float* w3l = (const float*)d_in[16];
    const float* w3r = (const float*)d_in[17];
    const float* b3  = (const float*)d_in[18];
    const float* ga3 = (const float*)d_in[19];
    const float* be3 = (const float*)d_in[20];
    const float* m3  = (const float*)d_in[21];
    const float* v3  = (const float*)d_in[22];

    float* out = (float*)d_out;

    float *agg, *h1, *h2, *wr;
    int   *cnt;
    cudaGetSymbolAddress((void**)&agg, g_agg);
    cudaGetSymbolAddress((void**)&h1,  g_h1);
    cudaGetSymbolAddress((void**)&h2,  g_h2);
    cudaGetSymbolAddress((void**)&wr,  g_wr);
    cudaGetSymbolAddress((void**)&cnt, g_cnt);

    cudaFuncSetAttribute(gemm_tc<128, 128>, cudaFuncAttributeMaxDynamicSharedMemorySize, GEMM_SMEM);
    cudaFuncSetAttribute(gemm_tc<128, 256>, cudaFuncAttributeMaxDynamicSharedMemorySize, GEMM_SMEM);
    cudaFuncSetAttribute(gemm_tc<256, 256>, cudaFuncAttributeMaxDynamicSharedMemorySize, GEMM_SMEM);

    const int T = 256;

    // ---- CSR build + rounded weights ----
    cudaMemsetAsync(cnt, 0, (size_t)M * sizeof(int), 0);
    hist_kernel<<<(E + T - 1) / T, T>>>(dst, E);
    scan_kernel<<<1, 1024>>>(M);
    fill_kernel<<<(E + T - 1) / T, T>>>(src, dst, E);
    {
        dim3 g(256, 6);
        prep_weights<<<g, T>>>(w1l, w1r, w2l, w2r, w3l, w3r);
    }

    const int gwarps = (M * 32 + T - 1) / T;   // one warp per node
    const int rtiles = (M + 127) / 128;

    // ---- layer 1: x[*,128] -> h1[*,128]  (self path rounds x in-loop)
    gather_kernel<128><<<gwarps, T>>>(x, agg, M);
    gemm_tc<128, 128><<<dim3(rtiles, 1), 256, GEMM_SMEM>>>(
        agg, x, wr + 0, wr + 16384, b1, ga1, be1, m1, v1, h1, M, 1, 1);

    // ---- layer 2: h1[*,128] -> h2[*,256]
    gather_kernel<128><<<gwarps, T>>>(h1, agg, M);
    gemm_tc<128, 256><<<dim3(rtiles, 2), 256, GEMM_SMEM>>>(
        agg, h1, wr + 32768, wr + 65536, b2, ga2, be2, m2, v2, h2, M, 1, 0);

    // ---- layer 3: h2[*,256] -> out[*,256]
    gather_kernel<256><<<gwarps, T>>>(h2, agg, M);
    gemm_tc<256, 256><<<dim3(rtiles, 2), 256, GEMM_SMEM>>>(
        agg, h2, wr + 98304, wr + 163840, b3, ga3, be3, m3, v3, out, M, 0, 0);
}

// round 14
// speedup vs baseline: 1.0122x; 1.0122x over previous
#include <cuda_runtime.h>
#include <math.h>
#include <stdint.h>

#define NMAX 100000
#define EMAX 2000000
#define EPSBN 1e-5f

// ---------------- scratch (device globals: no allocations allowed) ----------
__device__ float g_agg[(size_t)NMAX * 256];   // aggregation buffer (tf32-rounded)
__device__ float g_h1[(size_t)NMAX * 128];    // layer-1 output (tf32-rounded)
__device__ float g_h2[(size_t)NMAX * 256];    // layer-2 output (tf32-rounded)
__device__ float g_wr[229376];                // tf32-rounded weights ([K][N] layout)
__device__ int   g_cnt[NMAX];
__device__ int   g_off[NMAX + 1];
__device__ int   g_cur[NMAX];
__device__ int   g_csr[EMAX];
__device__ float g_invdeg[NMAX];

// ---------------- helpers -----------------------------------------------------
__device__ __forceinline__ unsigned f2tf(float f) {
    unsigned u;
    asm("cvt.rna.tf32.f32 %0, %1;" : "=r"(u) : "f"(f));
    return u;
}
__device__ __forceinline__ float tf32r(float f) { return __uint_as_float(f2tf(f)); }

__device__ __forceinline__ void mma_tf32(float* c, const unsigned* a, const unsigned* b) {
    asm volatile(
        "mma.sync.aligned.m16n8k8.row.col.f32.tf32.tf32.f32 "
        "{%0,%1,%2,%3}, {%4,%5,%6,%7}, {%8,%9}, {%0,%1,%2,%3};"
        : "+f"(c[0]), "+f"(c[1]), "+f"(c[2]), "+f"(c[3])
        : "r"(a[0]), "r"(a[1]), "r"(a[2]), "r"(a[3]), "r"(b[0]), "r"(b[1]));
}

__device__ __forceinline__ void cp16(void* dst, const void* src) {
    unsigned d = (unsigned)__cvta_generic_to_shared(dst);
    asm volatile("cp.async.cg.shared.global [%0], [%1], 16;" :: "r"(d), "l"(src));
}
__device__ __forceinline__ void cp_commit() { asm volatile("cp.async.commit_group;"); }
template<int N>
__device__ __forceinline__ void cp_wait() { asm volatile("cp.async.wait_group %0;" :: "n"(N)); }

// ---------------- CSR build --------------------------------------------------
__global__ void hist_kernel(const int* __restrict__ dst, int E) {
    int i = blockIdx.x * blockDim.x + threadIdx.x;
    if (i < E) atomicAdd(&g_cnt[dst[i]], 1);
}

__global__ void scan_kernel(int M) {
    __shared__ int part[1024];
    const int t = threadIdx.x;
    const int chunk = (M + 1023) >> 10;
    const int beg = t * chunk;
    const int end = min(beg + chunk, M);
    int s = 0;
    for (int i = beg; i < end; i++) s += g_cnt[i];
    part[t] = s;
    __syncthreads();
    for (int ofs = 1; ofs < 1024; ofs <<= 1) {
        int v = (t >= ofs) ? part[t - ofs] : 0;
        __syncthreads();
        part[t] += v;
        __syncthreads();
    }
    int run = (t > 0) ? part[t - 1] : 0;
    for (int i = beg; i < end; i++) {
        g_off[i] = run;
        g_cur[i] = run;
        g_invdeg[i] = 1.0f / fmaxf((float)g_cnt[i], 1.0f);
        run += g_cnt[i];
    }
    if (end == M) g_off[M] = run;
}

__global__ void fill_kernel(const int* __restrict__ src,
                            const int* __restrict__ dst, int E) {
    int i = blockIdx.x * blockDim.x + threadIdx.x;
    if (i < E) {
        int d = dst[i];
        int pos = atomicAdd(&g_cur[d], 1);
        g_csr[pos] = src[i];
    }
}

// ---------------- setup: tf32-rounded weights --------------------------------
__global__ void prep_weights(const float* __restrict__ w1l, const float* __restrict__ w1r,
                             const float* __restrict__ w2l, const float* __restrict__ w2r,
                             const float* __restrict__ w3l, const float* __restrict__ w3r) {
    const int seg = blockIdx.y;
    const float* src;
    float* dst;
    int n;
    switch (seg) {
        case 0:  src = w1l; dst = g_wr + 0;      n = 16384; break;
        case 1:  src = w1r; dst = g_wr + 16384;  n = 16384; break;
        case 2:  src = w2l; dst = g_wr + 32768;  n = 32768; break;
        case 3:  src = w2r; dst = g_wr + 65536;  n = 32768; break;
        case 4:  src = w3l; dst = g_wr + 98304;  n = 65536; break;
        default: src = w3r; dst = g_wr + 163840; n = 65536; break;
    }
    int i = blockIdx.x * blockDim.x + threadIdx.x;
    if (i < n) dst[i] = tf32r(src[i]);   // same [K][NOUT] layout, rounded
}

// ---------------- CSR gather: agg[n,:] = round_tf32(mean h[src,:]) -----------
// One warp per node (r5 form — fastest measured: 54.7us at D=128).
template<int D>
__global__ void gather_kernel(const float* __restrict__ h,
                              float* __restrict__ agg, int M) {
    const int warp = (blockIdx.x * blockDim.x + threadIdx.x) >> 5;
    const int lane = threadIdx.x & 31;
    if (warp >= M) return;
    const int beg = g_off[warp];
    const int end = g_off[warp + 1];

    float4 a0 = make_float4(0.f, 0.f, 0.f, 0.f);
    float4 a1 = make_float4(0.f, 0.f, 0.f, 0.f);

    for (int j0 = beg; j0 < end; j0 += 32) {
        const int myi = (j0 + lane < end) ? g_csr[j0 + lane] : 0;
        const int cnt = min(32, end - j0);
        for (int t = 0; t < cnt; t++) {
            const int s = __shfl_sync(0xffffffffu, myi, t);
            const float4* row = (const float4*)(h + (size_t)s * D);
            const float4 v = row[lane];
            a0.x += v.x; a0.y += v.y; a0.z += v.z; a0.w += v.w;
            if (D == 256) {
                const float4 w = row[lane + 32];
                a1.x += w.x; a1.y += w.y; a1.z += w.z; a1.w += w.w;
            }
        }
    }
    const float s = g_invdeg[warp];
    float4* outr = (float4*)(agg + (size_t)warp * D);
    outr[lane] = make_float4(tf32r(a0.x * s), tf32r(a0.y * s),
                             tf32r(a0.z * s), tf32r(a0.w * s));
    if (D == 256) {
        outr[lane + 32] = make_float4(tf32r(a1.x * s), tf32r(a1.y * s),
                                      tf32r(a1.z * s), tf32r(a1.w * s));
    }
}

// ---------------- fused dual GEMM (mma.sync, pre-rounded) + bias/ReLU/BN -----
// C = BN(ReLU( Aagg @ Wl + Aself @ Wr + bias ))
// Aagg/Wl/Wr pre-rounded to tf32; Aself rounded in-loop iff cvt_self (layer 1).
// Block 128x128, 128 threads (4 warps, 2x2), warp tile 64x64, BK=16, 4 stages.
#define STAGES 4
#define A_PITCH 20
#define B_PITCH 136
#define A_STRIDE (128 * A_PITCH)            // floats per A stage
#define B_STRIDE (16 * B_PITCH)             // floats per B stage
#define GEMM_SMEM ((STAGES * (A_STRIDE + B_STRIDE)) * 4)

template<int K, int NOUT>
__global__ void __launch_bounds__(128)
gemm_tc(const float* __restrict__ Aagg,
        const float* __restrict__ Aself,
        const float* __restrict__ Wl,
        const float* __restrict__ Wr,
        const float* __restrict__ bias,
        const float* __restrict__ gam,
        const float* __restrict__ bet,
        const float* __restrict__ mu,
        const float* __restrict__ var,
        float* __restrict__ C, int M, int round_out, int cvt_self) {
    extern __shared__ float sm[];
    float* As = sm;                          // [STAGES][128][A_PITCH]
    float* Bs = sm + STAGES * A_STRIDE;      // [STAGES][16][B_PITCH]

    const int tid  = threadIdx.x;
    const int lane = tid & 31;
    const int wid  = tid >> 5;
    const int wm   = wid & 1;           // warp row (0..1) -> 64 rows
    const int wn   = wid >> 1;          // warp col (0..1) -> 64 cols
    const int row0 = blockIdx.x * 128;
    const int col0 = blockIdx.y * 128;

    // cp.async load mappings (128 threads, 4 x 16B each for A and B)
    const int gr[4] = { min(row0 + ((0 * 128 + tid) >> 2), M - 1),
                        min(row0 + ((1 * 128 + tid) >> 2), M - 1),
                        min(row0 + ((2 * 128 + tid) >> 2), M - 1),
                        min(row0 + ((3 * 128 + tid) >> 2), M - 1) };

    float acc[4][8][4];
    #pragma unroll
    for (int i = 0; i < 4; i++)
        #pragma unroll
        for (int j = 0; j < 8; j++)
            #pragma unroll
            for (int q = 0; q < 4; q++) acc[i][j][q] = 0.0f;

    const int PH  = K / 16;
    const int NIT = 2 * PH;

    auto ISSUE = [&](int it, int st) {
        const int ph = (it >= PH) ? 1 : 0;
        const int kb = (ph ? it - PH : it) * 16;
        const float* A = ph ? Aself : Aagg;
        const float* W = ph ? Wr : Wl;
        float* as = As + st * A_STRIDE;
        float* bs = Bs + st * B_STRIDE;
        #pragma unroll
        for (int i = 0; i < 4; i++) {
            const int idx = i * 128 + tid;
            const int arr = idx >> 2, acc_ = (idx & 3) << 2;
            cp16(as + arr * A_PITCH + acc_, A + (size_t)gr[i] * K + kb + acc_);
            const int brr = idx >> 5, bcc = (idx & 31) << 2;
            cp16(bs + brr * B_PITCH + bcc, W + (size_t)(kb + brr) * NOUT + col0 + bcc);
        }
    };

    const int fr = lane >> 2;           // fragment row / B col
    const int fc = lane & 3;            // fragment k col

    auto COMPUTE = [&](int st, bool cv) {
        const float* as = As + st * A_STRIDE;
        const float* bs = Bs + st * B_STRIDE;
        #pragma unroll
        for (int ks = 0; ks < 2; ++ks) {
            const int kk = ks * 8;
            unsigned af[4][4], bf[8][2];
            #pragma unroll
            for (int mi = 0; mi < 4; mi++) {
                const int rb = wm * 64 + mi * 16;
                float f0 = as[(rb + fr)     * A_PITCH + kk + fc];
                float f1 = as[(rb + fr + 8) * A_PITCH + kk + fc];
                float f2 = as[(rb + fr)     * A_PITCH + kk + fc + 4];
                float f3 = as[(rb + fr + 8) * A_PITCH + kk + fc + 4];
                if (cv) {
                    af[mi][0] = f2tf(f0); af[mi][1] = f2tf(f1);
                    af[mi][2] = f2tf(f2); af[mi][3] = f2tf(f3);
                } else {
                    af[mi][0] = __float_as_uint(f0); af[mi][1] = __float_as_uint(f1);
                    af[mi][2] = __float_as_uint(f2); af[mi][3] = __float_as_uint(f3);
                }
            }
            #pragma unroll
            for (int ni = 0; ni < 8; ni++) {
                const int cb = wn * 64 + ni * 8 + fr;
                bf[ni][0] = __float_as_uint(bs[(kk + fc)     * B_PITCH + cb]);
                bf[ni][1] = __float_as_uint(bs[(kk + fc + 4) * B_PITCH + cb]);
            }
            #pragma unroll
            for (int mi = 0; mi < 4; mi++)
                #pragma unroll
                for (int ni = 0; ni < 8; ni++)
                    mma_tf32(acc[mi][ni], af[mi], bf[ni]);
        }
    };

    #pragma unroll
    for (int s = 0; s < STAGES - 1; ++s) {
        ISSUE(s, s);
        cp_commit();
    }

    for (int it = 0; it < NIT; ++it) {
        cp_wait<STAGES - 2>();
        __syncthreads();
        const int nx = it + STAGES - 1;
        if (nx < NIT) ISSUE(nx, nx % STAGES);
        cp_commit();
        COMPUTE(it % STAGES, cvt_self && (it >= PH));
    }

    // epilogue: bias -> ReLU -> BatchNorm(eval), optional tf32 rounding
    float sc[8][2], sh[8][2], bb[8][2];
    int   cbs[8];
    #pragma unroll
    for (int ni = 0; ni < 8; ni++) {
        const int cb = col0 + wn * 64 + ni * 8 + ((lane & 3) << 1);
        cbs[ni] = cb;
        #pragma unroll
        for (int j = 0; j < 2; j++) {
            const int c = cb + j;
            const float rs = rsqrtf(var[c] + EPSBN);
            sc[ni][j] = gam[c] * rs;
            sh[ni][j] = bet[c] - mu[c] * sc[ni][j];
            bb[ni][j] = bias[c];
        }
    }
    #pragma unroll
    for (int mi = 0; mi < 4; mi++) {
        const int rbase = row0 + wm * 64 + mi * 16 + (lane >> 2);
        #pragma unroll
        for (int h = 0; h < 2; h++) {
            const int r = rbase + h * 8;
            if (r < M) {
                #pragma unroll
                for (int ni = 0; ni < 8; ni++) {
                    float z0 = acc[mi][ni][h * 2 + 0] + bb[ni][0];
                    float z1 = acc[mi][ni][h * 2 + 1] + bb[ni][1];
                    z0 = fmaxf(z0, 0.0f) * sc[ni][0] + sh[ni][0];
                    z1 = fmaxf(z1, 0.0f) * sc[ni][1] + sh[ni][1];
                    float2 o;
                    o.x = round_out ? tf32r(z0) : z0;
                    o.y = round_out ? tf32r(z1) : z1;
                    *(float2*)(C + (size_t)r * NOUT + cbs[ni]) = o;
                }
            }
        }
    }
}

// ---------------- launcher ---------------------------------------------------
extern "C" void kernel_launch(void* const* d_in, const int* in_sizes, int n_in,
                              void* d_out, int out_size) {
    const float* x   = (const float*)d_in[0];
    const int*   ei  = (const int*)d_in[1];
    const int    E   = in_sizes[1] / 2;
    const int    M   = in_sizes[0] / 128;
    const int*   src = ei;
    const int*   dst = ei + E;

    const float* w1l = (const float*)d_in[2];
    const float* w1r = (const float*)d_in[3];
    const float* b1  = (const float*)d_in[4];
    const float* ga1 = (const float*)d_in[5];
    const float* be1 = (const float*)d_in[6];
    const float* m1  = (const float*)d_in[7];
    const float* v1  = (const float*)d_in[8];
    const float* w2l = (const float*)d_in[9];
    const float* w2r = (const float*)d_in[10];
    const float* b2  = (const float*)d_in[11];
    const float* ga2 = (const float*)d_in[12];
    const float* be2 = (const float*)d_in[13];
    const float* m2  = (const float*)d_in[14];
    const float* v2  = (const float*)d_in[15];
    const float* w3l = (const float*)d_in[16];
    const float* w3r = (const float*)d_in[17];
    const float* b3  = (const float*)d_in[18];
    const float* ga3 = (const float*)d_in[19];
    const float* be3 = (const float*)d_in[20];
    const float* m3  = (const float*)d_in[21];
    const float* v3  = (const float*)d_in[22];

    float* out = (float*)d_out;

    float *agg, *h1, *h2, *wr;
    int   *cnt;
    cudaGetSymbolAddress((void**)&agg, g_agg);
    cudaGetSymbolAddress((void**)&h1,  g_h1);
    cudaGetSymbolAddress((void**)&h2,  g_h2);
    cudaGetSymbolAddress((void**)&wr,  g_wr);
    cudaGetSymbolAddress((void**)&cnt, g_cnt);

    cudaFuncSetAttribute(gemm_tc<128, 128>, cudaFuncAttributeMaxDynamicSharedMemorySize, GEMM_SMEM);
    cudaFuncSetAttribute(gemm_tc<128, 256>, cudaFuncAttributeMaxDynamicSharedMemorySize, GEMM_SMEM);
    cudaFuncSetAttribute(gemm_tc<256, 256>, cudaFuncAttributeMaxDynamicSharedMemorySize, GEMM_SMEM);

    const int T = 256;

    // ---- CSR build + rounded weights ----
    cudaMemsetAsync(cnt, 0, (size_t)M * sizeof(int), 0);
    hist_kernel<<<(E + T - 1) / T, T>>>(dst, E);
    scan_kernel<<<1, 1024>>>(M);
    fill_kernel<<<(E + T - 1) / T, T>>>(src, dst, E);
    {
        dim3 g(256, 6);
        prep_weights<<<g, T>>>(w1l, w1r, w2l, w2r, w3l, w3r);
    }

    const int gwarps = (M * 32 + T - 1) / T;   // one warp per node
    const int rtiles = (M + 127) / 128;

    // ---- layer 1: x[*,128] -> h1[*,128]  (self path rounds x in-loop)
    gather_kernel<128><<<gwarps, T>>>(x, agg, M);
    gemm_tc<128, 128><<<dim3(rtiles, 1), 128, GEMM_SMEM>>>(
        agg, x, wr + 0, wr + 16384, b1, ga1, be1, m1, v1, h1, M, 1, 1);

    // ---- layer 2: h1[*,128] -> h2[*,256]
    gather_kernel<128><<<gwarps, T>>>(h1, agg, M);
    gemm_tc<128, 256><<<dim3(rtiles, 2), 128, GEMM_SMEM>>>(
        agg, h1, wr + 32768, wr + 65536, b2, ga2, be2, m2, v2, h2, M, 1, 0);

    // ---- layer 3: h2[*,256] -> out[*,256]
    gather_kernel<256><<<gwarps, T>>>(h2, agg, M);
    gemm_tc<256, 256><<<dim3(rtiles, 2), 128, GEMM_SMEM>>>(
        agg, h2, wr + 98304, wr + 163840, b3, ga3, be3, m3, v3, out, M, 0, 0);
}

// round 16
// speedup vs baseline: 1.3190x; 1.3031x over previous
#include <cuda_runtime.h>
#include <cuda_fp16.h>
#include <math.h>
#include <stdint.h>

#define NMAX 100000
#define EMAX 2000000
#define EPSBN 1e-5f

// ---------------- scratch (device globals: no allocations allowed) ----------
__device__ __align__(16) __half g_aggh[(size_t)NMAX * 256];  // agg (fp16)
__device__ __align__(16) __half g_h1h[(size_t)NMAX * 128];   // layer-1 out (fp16)
__device__ __align__(16) __half g_h2h[(size_t)NMAX * 256];   // layer-2 out (fp16)
__device__ __align__(16) __half g_xh[(size_t)NMAX * 128];    // fp16 copy of x
__device__ __align__(16) __half g_wt[229376];                // transposed fp16 weights [n][k]
__device__ int   g_cnt[NMAX];
__device__ int   g_off[NMAX + 1];
__device__ int   g_cur[NMAX];
__device__ int   g_csr[EMAX];
__device__ float g_invdeg[NMAX];

// ---------------- helpers -----------------------------------------------------
__device__ __forceinline__ void mma_f16(float* c, const unsigned* a, const unsigned* b) {
    asm volatile(
        "mma.sync.aligned.m16n8k16.row.col.f32.f16.f16.f32 "
        "{%0,%1,%2,%3}, {%4,%5,%6,%7}, {%8,%9}, {%0,%1,%2,%3};"
        : "+f"(c[0]), "+f"(c[1]), "+f"(c[2]), "+f"(c[3])
        : "r"(a[0]), "r"(a[1]), "r"(a[2]), "r"(a[3]), "r"(b[0]), "r"(b[1]));
}

__device__ __forceinline__ void cp16(void* dst, const void* src) {
    unsigned d = (unsigned)__cvta_generic_to_shared(dst);
    asm volatile("cp.async.cg.shared.global [%0], [%1], 16;" :: "r"(d), "l"(src));
}
__device__ __forceinline__ void cp_commit() { asm volatile("cp.async.commit_group;"); }
template<int N>
__device__ __forceinline__ void cp_wait() { asm volatile("cp.async.wait_group %0;" :: "n"(N)); }

// ---------------- CSR build --------------------------------------------------
__global__ void hist_kernel(const int* __restrict__ dst, int E) {
    int i = blockIdx.x * blockDim.x + threadIdx.x;
    if (i < E) atomicAdd(&g_cnt[dst[i]], 1);
}

__global__ void scan_kernel(int M) {
    __shared__ int part[1024];
    const int t = threadIdx.x;
    const int chunk = (M + 1023) >> 10;
    const int beg = t * chunk;
    const int end = min(beg + chunk, M);
    int s = 0;
    for (int i = beg; i < end; i++) s += g_cnt[i];
    part[t] = s;
    __syncthreads();
    for (int ofs = 1; ofs < 1024; ofs <<= 1) {
        int v = (t >= ofs) ? part[t - ofs] : 0;
        __syncthreads();
        part[t] += v;
        __syncthreads();
    }
    int run = (t > 0) ? part[t - 1] : 0;
    for (int i = beg; i < end; i++) {
        g_off[i] = run;
        g_cur[i] = run;
        g_invdeg[i] = 1.0f / fmaxf((float)g_cnt[i], 1.0f);
        run += g_cnt[i];
    }
    if (end == M) g_off[M] = run;
}

__global__ void fill_kernel(const int* __restrict__ src,
                            const int* __restrict__ dst, int E) {
    int i = blockIdx.x * blockDim.x + threadIdx.x;
    if (i < E) {
        int d = dst[i];
        int pos = atomicAdd(&g_cur[d], 1);
        g_csr[pos] = src[i];
    }
}

// ---------------- setup: fp16 x copy + transposed fp16 weights ---------------
__global__ void half_copy(const float* __restrict__ in, __half* __restrict__ out, int n4) {
    int i = blockIdx.x * blockDim.x + threadIdx.x;
    if (i < n4) {
        const float4 v = ((const float4*)in)[i];
        __half2 p0 = __floats2half2_rn(v.x, v.y);
        __half2 p1 = __floats2half2_rn(v.z, v.w);
        uint2 o;
        o.x = *(unsigned*)&p0;
        o.y = *(unsigned*)&p1;
        ((uint2*)out)[i] = o;
    }
}

// WT[n][k] = fp16(W[k][n])  (per segment)
__global__ void prep_weights(const float* __restrict__ w1l, const float* __restrict__ w1r,
                             const float* __restrict__ w2l, const float* __restrict__ w2r,
                             const float* __restrict__ w3l, const float* __restrict__ w3r) {
    const int seg = blockIdx.y;
    const float* src;
    __half* dst;
    int K, N;
    switch (seg) {
        case 0:  src = w1l; dst = g_wt + 0;      K = 128; N = 128; break;
        case 1:  src = w1r; dst = g_wt + 16384;  K = 128; N = 128; break;
        case 2:  src = w2l; dst = g_wt + 32768;  K = 128; N = 256; break;
        case 3:  src = w2r; dst = g_wt + 65536;  K = 128; N = 256; break;
        case 4:  src = w3l; dst = g_wt + 98304;  K = 256; N = 256; break;
        default: src = w3r; dst = g_wt + 163840; K = 256; N = 256; break;
    }
    int i = blockIdx.x * blockDim.x + threadIdx.x;
    if (i < K * N) {
        int k = i / N, n = i % N;
        dst[(size_t)n * K + k] = __float2half_rn(src[i]);
    }
}

// ---------------- CSR gather (fp16 rows): agg[n,:] = fp16(mean h[src,:]) -----
// One warp per node; fp32 accumulation.
template<int D>
__global__ void gather_h(const __half* __restrict__ h,
                         __half* __restrict__ agg, int M) {
    const int warp = (blockIdx.x * blockDim.x + threadIdx.x) >> 5;
    const int lane = threadIdx.x & 31;
    if (warp >= M) return;
    const int beg = g_off[warp];
    const int end = g_off[warp + 1];

    float a[8];
    #pragma unroll
    for (int q = 0; q < 8; q++) a[q] = 0.0f;

    for (int j0 = beg; j0 < end; j0 += 32) {
        const int myi = (j0 + lane < end) ? g_csr[j0 + lane] : 0;
        const int cnt = min(32, end - j0);
        for (int t = 0; t < cnt; t++) {
            const int s = __shfl_sync(0xffffffffu, myi, t);
            if (D == 128) {
                const uint2 u = ((const uint2*)(h + (size_t)s * D))[lane];
                const float2 f0 = __half22float2(*(const __half2*)&u.x);
                const float2 f1 = __half22float2(*(const __half2*)&u.y);
                a[0] += f0.x; a[1] += f0.y; a[2] += f1.x; a[3] += f1.y;
            } else {
                const uint4 u = ((const uint4*)(h + (size_t)s * D))[lane];
                const float2 f0 = __half22float2(*(const __half2*)&u.x);
                const float2 f1 = __half22float2(*(const __half2*)&u.y);
                const float2 f2 = __half22float2(*(const __half2*)&u.z);
                const float2 f3 = __half22float2(*(const __half2*)&u.w);
                a[0] += f0.x; a[1] += f0.y; a[2] += f1.x; a[3] += f1.y;
                a[4] += f2.x; a[5] += f2.y; a[6] += f3.x; a[7] += f3.y;
            }
        }
    }
    const float s = g_invdeg[warp];
    if (D == 128) {
        __half2 p0 = __floats2half2_rn(a[0] * s, a[1] * s);
        __half2 p1 = __floats2half2_rn(a[2] * s, a[3] * s);
        uint2 o;
        o.x = *(unsigned*)&p0; o.y = *(unsigned*)&p1;
        ((uint2*)(agg + (size_t)warp * D))[lane] = o;
    } else {
        __half2 p0 = __floats2half2_rn(a[0] * s, a[1] * s);
        __half2 p1 = __floats2half2_rn(a[2] * s, a[3] * s);
        __half2 p2 = __floats2half2_rn(a[4] * s, a[5] * s);
        __half2 p3 = __floats2half2_rn(a[6] * s, a[7] * s);
        uint4 o;
        o.x = *(unsigned*)&p0; o.y = *(unsigned*)&p1;
        o.z = *(unsigned*)&p2; o.w = *(unsigned*)&p3;
        ((uint4*)(agg + (size_t)warp * D))[lane] = o;
    }
}

// ---------------- fused dual GEMM (fp16 mma m16n8k16) + bias/ReLU/BN ---------
// C = BN(ReLU( Aagg @ Wl + Aself @ Wr + bias ));  A fp16 [m][k], WT fp16 [n][k].
// Block 128x128, 128 threads (4 warps 2x2), warp tile 64x64, BK=16, 4 stages.
#define STAGES 4
#define PITCH 24                              // halves; 12g+f mod 32 all-distinct
#define TSTRIDE (128 * PITCH)                 // halves per (A or B) stage
#define GEMM_SMEM (STAGES * 2 * TSTRIDE * 2)  // bytes = 48KB

template<int K, int NOUT, int OUT_HALF>
__global__ void __launch_bounds__(128)
gemm_f16(const __half* __restrict__ Aagg,
         const __half* __restrict__ Aself,
         const __half* __restrict__ WlT,
         const __half* __restrict__ WrT,
         const float* __restrict__ bias,
         const float* __restrict__ gam,
         const float* __restrict__ bet,
         const float* __restrict__ mu,
         const float* __restrict__ var,
         void* __restrict__ Cout, int M) {
    extern __shared__ __half sh[];
    __half* As = sh;                          // [STAGES][128][PITCH]
    __half* Bs = sh + STAGES * TSTRIDE;       // [STAGES][128][PITCH]

    const int tid  = threadIdx.x;
    const int lane = tid & 31;
    const int wid  = tid >> 5;
    const int wm   = wid & 1;           // warp row (0..1) -> 64 rows
    const int wn   = wid >> 1;          // warp col (0..1) -> 64 cols
    const int row0 = blockIdx.x * 128;
    const int col0 = blockIdx.y * 128;

    // cp.async mappings: tile 128 rows x 16 halves (32B) -> 2 x 16B per row.
    // thread handles idx = i*128+tid (i<2): row = idx>>1, seg = idx&1
    const int r0i = (0 * 128 + tid) >> 1, s0i = (0 * 128 + tid) & 1;
    const int r1i = (1 * 128 + tid) >> 1, s1i = (1 * 128 + tid) & 1;
    const int ga0 = min(row0 + r0i, M - 1);
    const int ga1 = min(row0 + r1i, M - 1);

    float acc[4][8][4];
    #pragma unroll
    for (int i = 0; i < 4; i++)
        #pragma unroll
        for (int j = 0; j < 8; j++)
            #pragma unroll
            for (int q = 0; q < 4; q++) acc[i][j][q] = 0.0f;

    const int PH  = K / 16;
    const int NIT = 2 * PH;

    auto ISSUE = [&](int it, int st) {
        const int ph = (it >= PH) ? 1 : 0;
        const int kb = (ph ? it - PH : it) * 16;
        const __half* A = ph ? Aself : Aagg;
        const __half* W = ph ? WrT : WlT;
        __half* as = As + st * TSTRIDE;
        __half* bs = Bs + st * TSTRIDE;
        cp16(as + r0i * PITCH + s0i * 8, A + (size_t)ga0 * K + kb + s0i * 8);
        cp16(as + r1i * PITCH + s1i * 8, A + (size_t)ga1 * K + kb + s1i * 8);
        cp16(bs + r0i * PITCH + s0i * 8, W + (size_t)(col0 + r0i) * K + kb + s0i * 8);
        cp16(bs + r1i * PITCH + s1i * 8, W + (size_t)(col0 + r1i) * K + kb + s1i * 8);
    };

    const int gid = lane >> 2;          // fragment row / B col
    const int fc  = lane & 3;           // k pair index

    auto COMPUTE = [&](int st) {
        const __half* as = As + st * TSTRIDE;
        const __half* bs = Bs + st * TSTRIDE;
        unsigned af[4][4], bf[8][2];
        #pragma unroll
        for (int mi = 0; mi < 4; mi++) {
            const int rb = wm * 64 + mi * 16;
            af[mi][0] = *(const unsigned*)&as[(rb + gid)     * PITCH + 2 * fc];
            af[mi][1] = *(const unsigned*)&as[(rb + gid + 8) * PITCH + 2 * fc];
            af[mi][2] = *(const unsigned*)&as[(rb + gid)     * PITCH + 2 * fc + 8];
            af[mi][3] = *(const unsigned*)&as[(rb + gid + 8) * PITCH + 2 * fc + 8];
        }
        #pragma unroll
        for (int ni = 0; ni < 8; ni++) {
            const int cb = wn * 64 + ni * 8 + gid;
            bf[ni][0] = *(const unsigned*)&bs[cb * PITCH + 2 * fc];
            bf[ni][1] = *(const unsigned*)&bs[cb * PITCH + 2 * fc + 8];
        }
        #pragma unroll
        for (int mi = 0; mi < 4; mi++)
            #pragma unroll
            for (int ni = 0; ni < 8; ni++)
                mma_f16(acc[mi][ni], af[mi], bf[ni]);
    };

    #pragma unroll
    for (int s = 0; s < STAGES - 1; ++s) {
        ISSUE(s, s);
        cp_commit();
    }

    for (int it = 0; it < NIT; ++it) {
        cp_wait<STAGES - 2>();
        __syncthreads();
        const int nx = it + STAGES - 1;
        if (nx < NIT) ISSUE(nx, nx % STAGES);
        cp_commit();
        COMPUTE(it % STAGES);
    }

    // epilogue: bias -> ReLU -> BatchNorm(eval)
    float sc[8][2], shf[8][2], bb[8][2];
    int   cbs[8];
    #pragma unroll
    for (int ni = 0; ni < 8; ni++) {
        const int cb = col0 + wn * 64 + ni * 8 + (fc << 1);
        cbs[ni] = cb;
        #pragma unroll
        for (int j = 0; j < 2; j++) {
            const int c = cb + j;
            const float rs = rsqrtf(var[c] + EPSBN);
            sc[ni][j] = gam[c] * rs;
            shf[ni][j] = bet[c] - mu[c] * sc[ni][j];
            bb[ni][j] = bias[c];
        }
    }
    #pragma unroll
    for (int mi = 0; mi < 4; mi++) {
        const int rbase = row0 + wm * 64 + mi * 16 + gid;
        #pragma unroll
        for (int h = 0; h < 2; h++) {
            const int r = rbase + h * 8;
            if (r < M) {
                #pragma unroll
                for (int ni = 0; ni < 8; ni++) {
                    float z0 = acc[mi][ni][h * 2 + 0] + bb[ni][0];
                    float z1 = acc[mi][ni][h * 2 + 1] + bb[ni][1];
                    z0 = fmaxf(z0, 0.0f) * sc[ni][0] + shf[ni][0];
                    z1 = fmaxf(z1, 0.0f) * sc[ni][1] + shf[ni][1];
                    if (OUT_HALF) {
                        __half2 p = __floats2half2_rn(z0, z1);
                        *(__half2*)((__half*)Cout + (size_t)r * NOUT + cbs[ni]) = p;
                    } else {
                        *(float2*)((float*)Cout + (size_t)r * NOUT + cbs[ni]) =
                            make_float2(z0, z1);
                    }
                }
            }
        }
    }
}

// ---------------- launcher ---------------------------------------------------
extern "C" void kernel_launch(void* const* d_in, const int* in_sizes, int n_in,
                              void* d_out, int out_size) {
    const float* x   = (const float*)d_in[0];
    const int*   ei  = (const int*)d_in[1];
    const int    E   = in_sizes[1] / 2;
    const int    M   = in_sizes[0] / 128;
    const int*   src = ei;
    const int*   dst = ei + E;

    const float* w1l = (const float*)d_in[2];
    const float* w1r = (const float*)d_in[3];
    const float* b1  = (const float*)d_in[4];
    const float* ga1 = (const float*)d_in[5];
    const float* be1 = (const float*)d_in[6];
    const float* m1  = (const float*)d_in[7];
    const float* v1  = (const float*)d_in[8];
    const float* w2l = (const float*)d_in[9];
    const float* w2r = (const float*)d_in[10];
    const float* b2  = (const float*)d_in[11];
    const float* ga2 = (const float*)d_in[12];
    const float* be2 = (const float*)d_in[13];
    const float* m2  = (const float*)d_in[14];
    const float* v2  = (const float*)d_in[15];
    const float* w3l = (const float*)d_in[16];
    const float* w3r = (const float*)d_in[17];
    const float* b3  = (const float*)d_in[18];
    const float* ga3 = (const float*)d_in[19];
    const float* be3 = (const float*)d_in[20];
    const float* m3  = (const float*)d_in[21];
    const float* v3  = (const float*)d_in[22];

    float* out = (float*)d_out;

    __half *aggh, *h1h, *h2h, *xh, *wt;
    int    *cnt;
    cudaGetSymbolAddress((void**)&aggh, g_aggh);
    cudaGetSymbolAddress((void**)&h1h,  g_h1h);
    cudaGetSymbolAddress((void**)&h2h,  g_h2h);
    cudaGetSymbolAddress((void**)&xh,   g_xh);
    cudaGetSymbolAddress((void**)&wt,   g_wt);
    cudaGetSymbolAddress((void**)&cnt,  g_cnt);

    cudaFuncSetAttribute(gemm_f16<128, 128, 1>, cudaFuncAttributeMaxDynamicSharedMemorySize, GEMM_SMEM);
    cudaFuncSetAttribute(gemm_f16<128, 256, 1>, cudaFuncAttributeMaxDynamicSharedMemorySize, GEMM_SMEM);
    cudaFuncSetAttribute(gemm_f16<256, 256, 0>, cudaFuncAttributeMaxDynamicSharedMemorySize, GEMM_SMEM);

    const int T = 256;

    // ---- CSR build + fp16 conversions ----
    cudaMemsetAsync(cnt, 0, (size_t)M * sizeof(int), 0);
    hist_kernel<<<(E + T - 1) / T, T>>>(dst, E);
    scan_kernel<<<1, 1024>>>(M);
    fill_kernel<<<(E + T - 1) / T, T>>>(src, dst, E);
    half_copy<<<(M * 32 + T - 1) / T, T>>>(x, xh, M * 32);   // M*128/4 float4s
    {
        dim3 g(256, 6);
        prep_weights<<<g, T>>>(w1l, w1r, w2l, w2r, w3l, w3r);
    }

    const int gwarps = (M * 32 + T - 1) / T;   // one warp per node
    const int rtiles = (M + 127) / 128;

    // ---- layer 1: xh[*,128] -> h1h[*,128]
    gather_h<128><<<gwarps, T>>>(xh, aggh, M);
    gemm_f16<128, 128, 1><<<dim3(rtiles, 1), 128, GEMM_SMEM>>>(
        aggh, xh, wt + 0, wt + 16384, b1, ga1, be1, m1, v1, h1h, M);

    // ---- layer 2: h1h[*,128] -> h2h[*,256]
    gather_h<128><<<gwarps, T>>>(h1h, aggh, M);
    gemm_f16<128, 256, 1><<<dim3(rtiles, 2), 128, GEMM_SMEM>>>(
        aggh, h1h, wt + 32768, wt + 65536, b2, ga2, be2, m2, v2, h2h, M);

    // ---- layer 3: h2h[*,256] -> out[*,256] (fp32)
    gather_h<256><<<gwarps, T>>>(h2h, aggh, M);
    gemm_f16<256, 256, 0><<<dim3(rtiles, 2), 128, GEMM_SMEM>>>(
        aggh, h2h, wt + 98304, wt + 163840, b3, ga3, be3, m3, v3, out, M);
}

// round 17
// speedup vs baseline: 1.3964x; 1.0587x over previous
#include <cuda_runtime.h>
#include <cuda_fp16.h>
#include <math.h>
#include <stdint.h>

#define NMAX 100000
#define EMAX 2000000
#define EPSBN 1e-5f

// ---------------- scratch (device globals: no allocations allowed) ----------
__device__ __align__(16) __half g_aggh[(size_t)NMAX * 256];  // agg (fp16)
__device__ __align__(16) __half g_h1h[(size_t)NMAX * 128];   // layer-1 out (fp16)
__device__ __align__(16) __half g_h2h[(size_t)NMAX * 256];   // layer-2 out (fp16)
__device__ __align__(16) __half g_xh[(size_t)NMAX * 128];    // fp16 copy of x
__device__ __align__(16) __half g_wt[229376];                // transposed fp16 weights [n][k]
__device__ int   g_cnt[NMAX];
__device__ int   g_off[NMAX + 1];
__device__ int   g_cur[NMAX];
__device__ int   g_csr[EMAX];
__device__ float g_invdeg[NMAX];

// ---------------- helpers -----------------------------------------------------
__device__ __forceinline__ void mma_f16(float* c, const unsigned* a, const unsigned* b) {
    asm volatile(
        "mma.sync.aligned.m16n8k16.row.col.f32.f16.f16.f32 "
        "{%0,%1,%2,%3}, {%4,%5,%6,%7}, {%8,%9}, {%0,%1,%2,%3};"
        : "+f"(c[0]), "+f"(c[1]), "+f"(c[2]), "+f"(c[3])
        : "r"(a[0]), "r"(a[1]), "r"(a[2]), "r"(a[3]), "r"(b[0]), "r"(b[1]));
}

__device__ __forceinline__ void ldm_x4(unsigned& r0, unsigned& r1, unsigned& r2,
                                       unsigned& r3, unsigned addr) {
    asm volatile("ldmatrix.sync.aligned.m8n8.x4.shared.b16 {%0,%1,%2,%3}, [%4];"
                 : "=r"(r0), "=r"(r1), "=r"(r2), "=r"(r3) : "r"(addr));
}

__device__ __forceinline__ void cp16(void* dst, const void* src) {
    unsigned d = (unsigned)__cvta_generic_to_shared(dst);
    asm volatile("cp.async.cg.shared.global [%0], [%1], 16;" :: "r"(d), "l"(src));
}
__device__ __forceinline__ void cp_commit() { asm volatile("cp.async.commit_group;"); }
template<int N>
__device__ __forceinline__ void cp_wait() { asm volatile("cp.async.wait_group %0;" :: "n"(N)); }

// ---------------- CSR build --------------------------------------------------
__global__ void hist_kernel(const int* __restrict__ dst, int E) {
    int i = blockIdx.x * blockDim.x + threadIdx.x;
    if (i < E) atomicAdd(&g_cnt[dst[i]], 1);
}

__global__ void scan_kernel(int M) {
    __shared__ int part[1024];
    const int t = threadIdx.x;
    const int chunk = (M + 1023) >> 10;
    const int beg = t * chunk;
    const int end = min(beg + chunk, M);
    int s = 0;
    for (int i = beg; i < end; i++) s += g_cnt[i];
    part[t] = s;
    __syncthreads();
    for (int ofs = 1; ofs < 1024; ofs <<= 1) {
        int v = (t >= ofs) ? part[t - ofs] : 0;
        __syncthreads();
        part[t] += v;
        __syncthreads();
    }
    int run = (t > 0) ? part[t - 1] : 0;
    for (int i = beg; i < end; i++) {
        g_off[i] = run;
        g_cur[i] = run;
        g_invdeg[i] = 1.0f / fmaxf((float)g_cnt[i], 1.0f);
        run += g_cnt[i];
    }
    if (end == M) g_off[M] = run;
}

__global__ void fill_kernel(const int* __restrict__ src,
                            const int* __restrict__ dst, int E) {
    int i = blockIdx.x * blockDim.x + threadIdx.x;
    if (i < E) {
        int d = dst[i];
        int pos = atomicAdd(&g_cur[d], 1);
        g_csr[pos] = src[i];
    }
}

// ---------------- setup: fp16 x copy + transposed fp16 weights ---------------
__global__ void half_copy(const float* __restrict__ in, __half* __restrict__ out, int n4) {
    int i = blockIdx.x * blockDim.x + threadIdx.x;
    if (i < n4) {
        const float4 v = ((const float4*)in)[i];
        __half2 p0 = __floats2half2_rn(v.x, v.y);
        __half2 p1 = __floats2half2_rn(v.z, v.w);
        uint2 o;
        o.x = *(unsigned*)&p0;
        o.y = *(unsigned*)&p1;
        ((uint2*)out)[i] = o;
    }
}

// WT[n][k] = fp16(W[k][n])  (per segment)
__global__ void prep_weights(const float* __restrict__ w1l, const float* __restrict__ w1r,
                             const float* __restrict__ w2l, const float* __restrict__ w2r,
                             const float* __restrict__ w3l, const float* __restrict__ w3r) {
    const int seg = blockIdx.y;
    const float* src;
    __half* dst;
    int K, N;
    switch (seg) {
        case 0:  src = w1l; dst = g_wt + 0;      K = 128; N = 128; break;
        case 1:  src = w1r; dst = g_wt + 16384;  K = 128; N = 128; break;
        case 2:  src = w2l; dst = g_wt + 32768;  K = 128; N = 256; break;
        case 3:  src = w2r; dst = g_wt + 65536;  K = 128; N = 256; break;
        case 4:  src = w3l; dst = g_wt + 98304;  K = 256; N = 256; break;
        default: src = w3r; dst = g_wt + 163840; K = 256; N = 256; break;
    }
    int i = blockIdx.x * blockDim.x + threadIdx.x;
    if (i < K * N) {
        int k = i / N, n = i % N;
        dst[(size_t)n * K + k] = __float2half_rn(src[i]);
    }
}

// ---------------- CSR gather D=128: half-warp per neighbor, 2 per iter -------
__device__ __forceinline__ void acc8(float* a, const uint4 u) {
    const float2 f0 = __half22float2(*(const __half2*)&u.x);
    const float2 f1 = __half22float2(*(const __half2*)&u.y);
    const float2 f2 = __half22float2(*(const __half2*)&u.z);
    const float2 f3 = __half22float2(*(const __half2*)&u.w);
    a[0] += f0.x; a[1] += f0.y; a[2] += f1.x; a[3] += f1.y;
    a[4] += f2.x; a[5] += f2.y; a[6] += f3.x; a[7] += f3.y;
}

__global__ void gather_h128(const __half* __restrict__ h,
                            __half* __restrict__ agg, int M) {
    const int warp = (blockIdx.x * blockDim.x + threadIdx.x) >> 5;
    const int lane = threadIdx.x & 31;
    if (warp >= M) return;
    const int beg = g_off[warp];
    const int end = g_off[warp + 1];
    const int hid = lane >> 4;     // which neighbor of the pair
    const int seg = lane & 15;     // 16 x uint4 = 256B row

    float a[8];
    #pragma unroll
    for (int q = 0; q < 8; q++) a[q] = 0.0f;

    for (int j0 = beg; j0 < end; j0 += 32) {
        const int myi = (j0 + lane < end) ? g_csr[j0 + lane] : 0;
        const int cnt = min(32, end - j0);
        int t = 0;
        for (; t + 1 < cnt; t += 2) {
            const int s = __shfl_sync(0xffffffffu, myi, t + hid);
            acc8(a, ((const uint4*)(h + (size_t)s * 128))[seg]);
        }
        if (t < cnt) {
            const int s = __shfl_sync(0xffffffffu, myi, t);
            if (hid == 0)
                acc8(a, ((const uint4*)(h + (size_t)s * 128))[seg]);
        }
    }
    #pragma unroll
    for (int q = 0; q < 8; q++) a[q] += __shfl_xor_sync(0xffffffffu, a[q], 16);

    if (hid == 0) {
        const float s = g_invdeg[warp];
        __half2 p0 = __floats2half2_rn(a[0] * s, a[1] * s);
        __half2 p1 = __floats2half2_rn(a[2] * s, a[3] * s);
        __half2 p2 = __floats2half2_rn(a[4] * s, a[5] * s);
        __half2 p3 = __floats2half2_rn(a[6] * s, a[7] * s);
        uint4 o;
        o.x = *(unsigned*)&p0; o.y = *(unsigned*)&p1;
        o.z = *(unsigned*)&p2; o.w = *(unsigned*)&p3;
        ((uint4*)(agg + (size_t)warp * 128))[seg] = o;
    }
}

// ---------------- CSR gather D=256: full warp per row, unroll x2 -------------
__global__ void gather_h256(const __half* __restrict__ h,
                            __half* __restrict__ agg, int M) {
    const int warp = (blockIdx.x * blockDim.x + threadIdx.x) >> 5;
    const int lane = threadIdx.x & 31;
    if (warp >= M) return;
    const int beg = g_off[warp];
    const int end = g_off[warp + 1];

    float a[8];
    #pragma unroll
    for (int q = 0; q < 8; q++) a[q] = 0.0f;

    for (int j0 = beg; j0 < end; j0 += 32) {
        const int myi = (j0 + lane < end) ? g_csr[j0 + lane] : 0;
        const int cnt = min(32, end - j0);
        int t = 0;
        for (; t + 1 < cnt; t += 2) {
            const int s0 = __shfl_sync(0xffffffffu, myi, t);
            const int s1 = __shfl_sync(0xffffffffu, myi, t + 1);
            const uint4 u0 = ((const uint4*)(h + (size_t)s0 * 256))[lane];
            const uint4 u1 = ((const uint4*)(h + (size_t)s1 * 256))[lane];
            acc8(a, u0);
            acc8(a, u1);
        }
        if (t < cnt) {
            const int s0 = __shfl_sync(0xffffffffu, myi, t);
            acc8(a, ((const uint4*)(h + (size_t)s0 * 256))[lane]);
        }
    }
    const float s = g_invdeg[warp];
    __half2 p0 = __floats2half2_rn(a[0] * s, a[1] * s);
    __half2 p1 = __floats2half2_rn(a[2] * s, a[3] * s);
    __half2 p2 = __floats2half2_rn(a[4] * s, a[5] * s);
    __half2 p3 = __floats2half2_rn(a[6] * s, a[7] * s);
    uint4 o;
    o.x = *(unsigned*)&p0; o.y = *(unsigned*)&p1;
    o.z = *(unsigned*)&p2; o.w = *(unsigned*)&p3;
    ((uint4*)(agg + (size_t)warp * 256))[lane] = o;
}

// ---------------- fused dual GEMM (fp16 mma m16n8k16 + ldmatrix) -------------
// C = BN(ReLU( Aagg @ Wl + Aself @ Wr + bias ));  A fp16 [m][k], WT fp16 [n][k].
// Block 128x128, 128 threads (4 warps 2x2), warp tile 64x64, BK=16, 4 stages.
#define STAGES 4
#define PITCH 24                              // halves; 48B rows, conflict-free
#define TSTRIDE (128 * PITCH)                 // halves per (A or B) stage
#define GEMM_SMEM (STAGES * 2 * TSTRIDE * 2)  // bytes = 48KB

template<int K, int NOUT, int OUT_HALF>
__global__ void __launch_bounds__(128)
gemm_f16(const __half* __restrict__ Aagg,
         const __half* __restrict__ Aself,
         const __half* __restrict__ WlT,
         const __half* __restrict__ WrT,
         const float* __restrict__ bias,
         const float* __restrict__ gam,
         const float* __restrict__ bet,
         const float* __restrict__ mu,
         const float* __restrict__ var,
         void* __restrict__ Cout, int M) {
    extern __shared__ __half sh[];
    __half* As = sh;                          // [STAGES][128][PITCH]
    __half* Bs = sh + STAGES * TSTRIDE;       // [STAGES][128][PITCH]

    const int tid  = threadIdx.x;
    const int lane = tid & 31;
    const int wid  = tid >> 5;
    const int wm   = wid & 1;           // warp row (0..1) -> 64 rows
    const int wn   = wid >> 1;          // warp col (0..1) -> 64 cols
    const int row0 = blockIdx.x * 128;
    const int col0 = blockIdx.y * 128;

    // cp.async mappings: tile 128 rows x 16 halves (32B) -> 2 x 16B per row.
    const int r0i = (0 * 128 + tid) >> 1, s0i = (0 * 128 + tid) & 1;
    const int r1i = (1 * 128 + tid) >> 1, s1i = (1 * 128 + tid) & 1;
    const int ga0 = min(row0 + r0i, M - 1);
    const int ga1 = min(row0 + r1i, M - 1);

    float acc[4][8][4];
    #pragma unroll
    for (int i = 0; i < 4; i++)
        #pragma unroll
        for (int j = 0; j < 8; j++)
            #pragma unroll
            for (int q = 0; q < 4; q++) acc[i][j][q] = 0.0f;

    const int PH  = K / 16;
    const int NIT = 2 * PH;

    auto ISSUE = [&](int it, int st) {
        const int ph = (it >= PH) ? 1 : 0;
        const int kb = (ph ? it - PH : it) * 16;
        const __half* A = ph ? Aself : Aagg;
        const __half* W = ph ? WrT : WlT;
        __half* as = As + st * TSTRIDE;
        __half* bs = Bs + st * TSTRIDE;
        cp16(as + r0i * PITCH + s0i * 8, A + (size_t)ga0 * K + kb + s0i * 8);
        cp16(as + r1i * PITCH + s1i * 8, A + (size_t)ga1 * K + kb + s1i * 8);
        cp16(bs + r0i * PITCH + s0i * 8, W + (size_t)(col0 + r0i) * K + kb + s0i * 8);
        cp16(bs + r1i * PITCH + s1i * 8, W + (size_t)(col0 + r1i) * K + kb + s1i * 8);
    };

    const int gid = lane >> 2;          // fragment row / B col
    const int fc  = lane & 3;           // k pair index

    // ldmatrix lane mapping (precomputed offsets in halves)
    const int lt = lane >> 3;           // tile index within x4
    const int lr = lane & 7;            // row within 8x8 tile
    // A x4: tiles {r,k0},{r+8,k0},{r,k8},{r+8,k8}
    const int a_row_off = (lt & 1) * 8 + lr;
    const int a_k_off   = (lt >> 1) * 8;
    // B x4 (two n-fragments): tiles {n,k0},{n,k8},{n+8,k0},{n+8,k8}
    const int b_row_off = (lt >> 1) * 8 + lr;
    const int b_k_off   = (lt & 1) * 8;

    auto COMPUTE = [&](int st) {
        const unsigned abase = (unsigned)__cvta_generic_to_shared(As + st * TSTRIDE);
        const unsigned bbase = (unsigned)__cvta_generic_to_shared(Bs + st * TSTRIDE);
        unsigned af[4][4], bf[8][2];
        #pragma unroll
        for (int mi = 0; mi < 4; mi++) {
            const int row = wm * 64 + mi * 16 + a_row_off;
            ldm_x4(af[mi][0], af[mi][1], af[mi][2], af[mi][3],
                   abase + (row * PITCH + a_k_off) * 2);
        }
        #pragma unroll
        for (int nn = 0; nn < 4; nn++) {
            const int col = wn * 64 + nn * 16 + b_row_off;
            ldm_x4(bf[2 * nn][0], bf[2 * nn][1], bf[2 * nn + 1][0], bf[2 * nn + 1][1],
                   bbase + (col * PITCH + b_k_off) * 2);
        }
        #pragma unroll
        for (int mi = 0; mi < 4; mi++)
            #pragma unroll
            for (int ni = 0; ni < 8; ni++)
                mma_f16(acc[mi][ni], af[mi], bf[ni]);
    };

    #pragma unroll
    for (int s = 0; s < STAGES - 1; ++s) {
        ISSUE(s, s);
        cp_commit();
    }

    for (int it = 0; it < NIT; ++it) {
        cp_wait<STAGES - 2>();
        __syncthreads();
        const int nx = it + STAGES - 1;
        if (nx < NIT) ISSUE(nx, nx % STAGES);
        cp_commit();
        COMPUTE(it % STAGES);
    }

    // epilogue: bias -> ReLU -> BatchNorm(eval)
    float sc[8][2], shf[8][2], bb[8][2];
    int   cbs[8];
    #pragma unroll
    for (int ni = 0; ni < 8; ni++) {
        const int cb = col0 + wn * 64 + ni * 8 + (fc << 1);
        cbs[ni] = cb;
        #pragma unroll
        for (int j = 0; j < 2; j++) {
            const int c = cb + j;
            const float rs = rsqrtf(var[c] + EPSBN);
            sc[ni][j] = gam[c] * rs;
            shf[ni][j] = bet[c] - mu[c] * sc[ni][j];
            bb[ni][j] = bias[c];
        }
    }
    #pragma unroll
    for (int mi = 0; mi < 4; mi++) {
        const int rbase = row0 + wm * 64 + mi * 16 + gid;
        #pragma unroll
        for (int h = 0; h < 2; h++) {
            const int r = rbase + h * 8;
            if (r < M) {
                #pragma unroll
                for (int ni = 0; ni < 8; ni++) {
                    float z0 = acc[mi][ni][h * 2 + 0] + bb[ni][0];
                    float z1 = acc[mi][ni][h * 2 + 1] + bb[ni][1];
                    z0 = fmaxf(z0, 0.0f) * sc[ni][0] + shf[ni][0];
                    z1 = fmaxf(z1, 0.0f) * sc[ni][1] + shf[ni][1];
                    if (OUT_HALF) {
                        __half2 p = __floats2half2_rn(z0, z1);
                        *(__half2*)((__half*)Cout + (size_t)r * NOUT + cbs[ni]) = p;
                    } else {
                        *(float2*)((float*)Cout + (size_t)r * NOUT + cbs[ni]) =
                            make_float2(z0, z1);
                    }
                }
            }
        }
    }
}

// ---------------- launcher ---------------------------------------------------
extern "C" void kernel_launch(void* const* d_in, const int* in_sizes, int n_in,
                              void* d_out, int out_size) {
    const float* x   = (const float*)d_in[0];
    const int*   ei  = (const int*)d_in[1];
    const int    E   = in_sizes[1] / 2;
    const int    M   = in_sizes[0] / 128;
    const int*   src = ei;
    const int*   dst = ei + E;

    const float* w1l = (const float*)d_in[2];
    const float* w1r = (const float*)d_in[3];
    const float* b1  = (const float*)d_in[4];
    const float* ga1 = (const float*)d_in[5];
    const float* be1 = (const float*)d_in[6];
    const float* m1  = (const float*)d_in[7];
    const float* v1  = (const float*)d_in[8];
    const float* w2l = (const float*)d_in[9];
    const float* w2r = (const float*)d_in[10];
    const float* b2  = (const float*)d_in[11];
    const float* ga2 = (const float*)d_in[12];
    const float* be2 = (const float*)d_in[13];
    const float* m2  = (const float*)d_in[14];
    const float* v2  = (const float*)d_in[15];
    const float* w3l = (const float*)d_in[16];
    const float* w3r = (const float*)d_in[17];
    const float* b3  = (const float*)d_in[18];
    const float* ga3 = (const float*)d_in[19];
    const float* be3 = (const float*)d_in[20];
    const float* m3  = (const float*)d_in[21];
    const float* v3  = (const float*)d_in[22];

    float* out = (float*)d_out;

    __half *aggh, *h1h, *h2h, *xh, *wt;
    int    *cnt;
    cudaGetSymbolAddress((void**)&aggh, g_aggh);
    cudaGetSymbolAddress((void**)&h1h,  g_h1h);
    cudaGetSymbolAddress((void**)&h2h,  g_h2h);
    cudaGetSymbolAddress((void**)&xh,   g_xh);
    cudaGetSymbolAddress((void**)&wt,   g_wt);
    cudaGetSymbolAddress((void**)&cnt,  g_cnt);

    cudaFuncSetAttribute(gemm_f16<128, 128, 1>, cudaFuncAttributeMaxDynamicSharedMemorySize, GEMM_SMEM);
    cudaFuncSetAttribute(gemm_f16<128, 256, 1>, cudaFuncAttributeMaxDynamicSharedMemorySize, GEMM_SMEM);
    cudaFuncSetAttribute(gemm_f16<256, 256, 0>, cudaFuncAttributeMaxDynamicSharedMemorySize, GEMM_SMEM);

    const int T = 256;

    // ---- CSR build + fp16 conversions ----
    cudaMemsetAsync(cnt, 0, (size_t)M * sizeof(int), 0);
    hist_kernel<<<(E + T - 1) / T, T>>>(dst, E);
    scan_kernel<<<1, 1024>>>(M);
    fill_kernel<<<(E + T - 1) / T, T>>>(src, dst, E);
    half_copy<<<(M * 32 + T - 1) / T, T>>>(x, xh, M * 32);
    {
        dim3 g(256, 6);
        prep_weights<<<g, T>>>(w1l, w1r, w2l, w2r, w3l, w3r);
    }

    const int gwarps = (M * 32 + T - 1) / T;   // one warp per node
    const int rtiles = (M + 127) / 128;

    // ---- layer 1: xh[*,128] -> h1h[*,128]
    gather_h128<<<gwarps, T>>>(xh, aggh, M);
    gemm_f16<128, 128, 1><<<dim3(rtiles, 1), 128, GEMM_SMEM>>>(
        aggh, xh, wt + 0, wt + 16384, b1, ga1, be1, m1, v1, h1h, M);

    // ---- layer 2: h1h[*,128] -> h2h[*,256]
    gather_h128<<<gwarps, T>>>(h1h, aggh, M);
    gemm_f16<128, 256, 1><<<dim3(rtiles, 2), 128, GEMM_SMEM>>>(
        aggh, h1h, wt + 32768, wt + 65536, b2, ga2, be2, m2, v2, h2h, M);

    // ---- layer 3: h2h[*,256] -> out[*,256] (fp32)
    gather_h256<<<gwarps, T>>>(h2h, aggh, M);
    gemm_f16<256, 256, 0><<<dim3(rtiles, 2), 128, GEMM_SMEM>>>(
        aggh, h2h, wt + 98304, wt + 163840, b3, ga3, be3, m3, v3, out, M);
}